// round 6
// baseline (speedup 1.0000x reference)
#include <cuda_runtime.h>
#include <math.h>

#define Bc 4
#define Nc 5
#define Cc 64
#define Hc 96
#define Wc 288
#define HWc (Hc * Wc)

// DECAY_WEIGHTS = softmax([1.0, 0.5])
#define W0c 0.6224593312018546f
#define W1c 0.3775406687981454f

// score tiling
#define SPX 16
#define SCG 16
#define SCPT 4

// fuse tiling
#define GPX 32

__device__ float g_theta[Bc * Nc * 6];
__device__ float g_mask[Bc * HWc];
__device__ float g_dmask[Bc * HWc];
// channel-last scratch: x0t[b][n][p][c], as float4 over c (16 float4 per pixel)
__device__ float4 g_x0t[(size_t)Bc * Nc * HWc * (Cc / 4)];

// ---------------------------------------------------------------------------
// Kernel T: build 2x3 affine thetas from pairwise_t_matrix[b, 0, n]
// ---------------------------------------------------------------------------
__global__ void theta_kernel(const float* __restrict__ pt) {
    int t = threadIdx.x;
    if (t >= Bc * Nc) return;
    int b = t / Nc, n = t % Nc;
    const float* P = pt + ((size_t)(b * Nc + 0) * Nc + n) * 16;  // 4x4 row-major
    float* th = g_theta + t * 6;
    th[0] = P[0];
    th[1] = P[1] * ((float)Hc / (float)Wc);
    th[2] = P[3] / (4.0f * 0.4f * (float)Wc) * 2.0f;
    th[3] = P[4] * ((float)Wc / (float)Hc);
    th[4] = P[5];
    th[5] = P[7] / (4.0f * 0.4f * (float)Hc) * 2.0f;
}

// ---------------------------------------------------------------------------
// Kernel A: per-pixel confidence -> binary mask; ALSO emits channel-last
// transposed copy of x0 (smem-staged, coalesced writes).
// ---------------------------------------------------------------------------
__global__ __launch_bounds__(SPX * SCG)
void score_kernel(const float* __restrict__ x0, const float* __restrict__ x1,
                  const float* __restrict__ mlp_w, const float* __restrict__ mlp_b) {
    __shared__ float  sm_ss[2][4][SCG][SPX];
    __shared__ float  sm_mm[2][4][SCG][SPX];
    __shared__ float4 sm_t[Nc][SPX][SCG + 1];   // +1 pad: conflict-free STS.128

    int tx = threadIdx.x;          // pixel in tile
    int ty = threadIdx.y;          // channel group (c4 index)
    int p0 = blockIdx.x * SPX;
    int p  = p0 + tx;
    int b  = blockIdx.y;
    int c0 = ty * SCPT;

    float w[SCPT];
    #pragma unroll
    for (int cc = 0; cc < SCPT; cc++) w[cc] = __ldg(mlp_w + c0 + cc);

    #pragma unroll
    for (int f = 0; f < 2; f++) {
        const float* xf = (f == 0) ? x0 : x1;
        const float* base = xf + (size_t)b * Nc * Cc * HWc + (size_t)c0 * HWc + p;

        float e[SCPT];
        #pragma unroll
        for (int cc = 0; cc < SCPT; cc++) e[cc] = base[(size_t)cc * HWc];
        if (f == 0) sm_t[0][tx][ty] = make_float4(e[0], e[1], e[2], e[3]);

        #pragma unroll
        for (int k = 0; k < 4; k++) {
            const float* nb = base + (size_t)(k + 1) * Cc * HWc;
            float nv[SCPT];
            #pragma unroll
            for (int cc = 0; cc < SCPT; cc++) nv[cc] = nb[(size_t)cc * HWc];
            if (f == 0) sm_t[k + 1][tx][ty] = make_float4(nv[0], nv[1], nv[2], nv[3]);
            float ss = 0.f, mm = 0.f;
            #pragma unroll
            for (int cc = 0; cc < SCPT; cc++) {
                ss = fmaf(e[cc], nv[cc], ss);
                mm = fmaf(w[cc], nv[cc], mm);
            }
            sm_ss[f][k][ty][tx] = ss;
            sm_mm[f][k][ty][tx] = mm;
        }
    }
    __syncthreads();

    // coalesced writeout of the transposed tile: 5 float4 per thread
    {
        int tid = ty * SPX + tx;
        float4* xt = g_x0t + (size_t)b * Nc * HWc * (Cc / 4);
        #pragma unroll
        for (int i = 0; i < Nc; i++) {
            int q  = tid + i * (SPX * SCG);
            int n  = q >> 8;            // / 256
            int r  = q & 255;
            int pp = r >> 4;            // / 16
            int c4 = r & 15;
            xt[((size_t)n * HWc + p0 + pp) * (Cc / 4) + c4] = sm_t[n][pp][c4];
        }
    }

    if (ty == 0) {
        float bb = __ldg(mlp_b);
        float conf = 0.f;
        const float dw[2] = {W0c, W1c};
        #pragma unroll
        for (int f = 0; f < 2; f++) {
            float s[4], m[4];
            #pragma unroll
            for (int k = 0; k < 4; k++) {
                float ss = 0.f, mm = 0.f;
                #pragma unroll
                for (int cg = 0; cg < SCG; cg++) {
                    ss += sm_ss[f][k][cg][tx];
                    mm += sm_mm[f][k][cg][tx];
                }
                s[k] = ss * 0.125f;
                m[k] = mm;
            }
            float mx = fmaxf(fmaxf(s[0], s[1]), fmaxf(s[2], s[3]));
            float sum = 0.f, acc = 0.f;
            #pragma unroll
            for (int k = 0; k < 4; k++) {
                float e2 = expf(s[k] - mx);
                sum += e2;
                acc = fmaf(e2, m[k], acc);
            }
            float z = acc / sum + bb;
            conf += dw[f] / (1.f + expf(-z));
        }
        g_mask[b * HWc + p] = (conf > 0.5f) ? 1.0f : 0.0f;
    }
}

// ---------------------------------------------------------------------------
// Kernel B: 3x3 max dilation (SAME), all batches
// ---------------------------------------------------------------------------
__global__ void dilate_kernel() {
    int p = blockIdx.x * blockDim.x + threadIdx.x;
    int b = blockIdx.y;
    if (p >= HWc) return;
    int i = p / Wc, j = p % Wc;
    float m = 0.f;
    #pragma unroll
    for (int di = -1; di <= 1; di++) {
        int ii = i + di;
        if (ii < 0 || ii >= Hc) continue;
        #pragma unroll
        for (int dj = -1; dj <= 1; dj++) {
            int jj = j + dj;
            if (jj < 0 || jj >= Wc) continue;
            m = fmaxf(m, g_mask[b * HWc + ii * Wc + jj]);
        }
    }
    g_dmask[b * HWc + p] = m;
}

// ---------------------------------------------------------------------------
// Kernel C: warp + 5-way attention fusion, reading channel-last x0t.
//   warp = 2 pixels; 16 lanes = 64 channels (float4/lane).
//   Per pixel: 10 LDG.128 total (vs 40 LDG.32 before).
// ---------------------------------------------------------------------------
__global__ __launch_bounds__(512, 2)
void fuse_kernel(float* __restrict__ out) {
    __shared__ int4   sm_ti[Nc][GPX];
    __shared__ float4 sm_tw[Nc][GPX];
    __shared__ float  sm_o[Cc][GPX + 1];

    int tid = threadIdx.x;
    int b   = blockIdx.y;
    int p0  = blockIdx.x * GPX;

    // ---- tap precompute: one thread per (frame, pixel) ----
    if (tid < Nc * GPX) {
        int n  = tid >> 5;
        int l  = tid & 31;
        int pp = p0 + l;
        int i = pp / Wc, j = pp - i * Wc;
        float gx = -1.f + 2.f * (float)j / (float)(Wc - 1);
        float gy = -1.f + 2.f * (float)i / (float)(Hc - 1);

        const float* th = g_theta + (b * Nc + n) * 6;
        float g0 = fmaf(th[0], gx, fmaf(th[1], gy, th[2]));
        float g1 = fmaf(th[3], gx, fmaf(th[4], gy, th[5]));
        float pxf = (g0 + 1.f) * 0.5f * (float)(Wc - 1);
        float pyf = (g1 + 1.f) * 0.5f * (float)(Hc - 1);
        float x0f = floorf(pxf), y0f = floorf(pyf);
        float wx = pxf - x0f, wy = pyf - y0f;
        int xi = (int)x0f, yi = (int)y0f;

        int r0 = min(max(yi, 0), Hc - 1) * Wc;
        int r1 = min(max(yi + 1, 0), Hc - 1) * Wc;
        float wy0 = (yi >= 0 && yi <= Hc - 1) ? (1.f - wy) : 0.f;
        float wy1 = (yi + 1 >= 0 && yi + 1 <= Hc - 1) ? wy : 0.f;

        int bx = min(max(xi, 0), Wc - 2);
        int sh = xi - bx;
        float ax0, ax1;
        if (sh == 0)        { ax0 = 1.f - wx; ax1 = wx;       }
        else if (sh == -1)  { ax0 = wx;       ax1 = 0.f;      }
        else if (sh == 1)   { ax0 = 0.f;      ax1 = 1.f - wx; }
        else                { ax0 = 0.f;      ax1 = 0.f;      }

        float m00 = 1.f, m01 = 1.f, m10 = 1.f, m11 = 1.f;
        if (n > 0) {
            const float* dm = g_dmask + b * HWc;
            m00 = dm[r0 + bx]; m01 = dm[r0 + bx + 1];
            m10 = dm[r1 + bx]; m11 = dm[r1 + bx + 1];
        }

        sm_ti[n][l] = make_int4(r0 + bx, r0 + bx + 1, r1 + bx, r1 + bx + 1);
        sm_tw[n][l] = make_float4(ax0 * wy0 * m00, ax1 * wy0 * m01,
                                  ax0 * wy1 * m10, ax1 * wy1 * m11);
    }
    __syncthreads();

    int wrp  = tid >> 5;
    int lane = tid & 31;
    int half = lane >> 4;
    int c4   = lane & 15;
    int px   = wrp * 2 + half;      // local pixel (0..31)

    const float4* xt = g_x0t + (size_t)b * Nc * HWc * (Cc / 4) + c4;

    float4 v[Nc];
    float  s[Nc];
    #pragma unroll
    for (int k = 0; k < Nc; k++) {
        int4   ti = sm_ti[k][px];
        float4 tw = sm_tw[k][px];
        const float4* fb = xt + (size_t)k * HWc * (Cc / 4);
        float4 t0 = __ldg(fb + (size_t)ti.x * (Cc / 4));
        float4 t1 = __ldg(fb + (size_t)ti.y * (Cc / 4));
        float4 t2 = __ldg(fb + (size_t)ti.z * (Cc / 4));
        float4 t3 = __ldg(fb + (size_t)ti.w * (Cc / 4));
        float4 val;
        val.x = fmaf(tw.x, t0.x, fmaf(tw.y, t1.x, fmaf(tw.z, t2.x, tw.w * t3.x)));
        val.y = fmaf(tw.x, t0.y, fmaf(tw.y, t1.y, fmaf(tw.z, t2.y, tw.w * t3.y)));
        val.z = fmaf(tw.x, t0.z, fmaf(tw.y, t1.z, fmaf(tw.z, t2.z, tw.w * t3.z)));
        val.w = fmaf(tw.x, t0.w, fmaf(tw.y, t1.w, fmaf(tw.z, t2.w, tw.w * t3.w)));
        v[k] = val;
        float d = fmaf(v[0].x, val.x, fmaf(v[0].y, val.y,
                  fmaf(v[0].z, val.z, v[0].w * val.w)));
        d += __shfl_xor_sync(0xffffffffu, d, 1);
        d += __shfl_xor_sync(0xffffffffu, d, 2);
        d += __shfl_xor_sync(0xffffffffu, d, 4);
        d += __shfl_xor_sync(0xffffffffu, d, 8);
        s[k] = d * 0.125f;
    }

    // softmax over 5 (every lane has its pixel's full scores)
    float mx = s[0];
    #pragma unroll
    for (int k = 1; k < Nc; k++) mx = fmaxf(mx, s[k]);
    float a[Nc], sum = 0.f;
    #pragma unroll
    for (int k = 0; k < Nc; k++) { a[k] = __expf(s[k] - mx); sum += a[k]; }
    float inv = 1.f / sum;

    float4 o;
    o.x = fmaf(a[4], v[4].x, fmaf(a[3], v[3].x, fmaf(a[2], v[2].x, fmaf(a[1], v[1].x, a[0] * v[0].x)))) * inv;
    o.y = fmaf(a[4], v[4].y, fmaf(a[3], v[3].y, fmaf(a[2], v[2].y, fmaf(a[1], v[1].y, a[0] * v[0].y)))) * inv;
    o.z = fmaf(a[4], v[4].z, fmaf(a[3], v[3].z, fmaf(a[2], v[2].z, fmaf(a[1], v[1].z, a[0] * v[0].z)))) * inv;
    o.w = fmaf(a[4], v[4].w, fmaf(a[3], v[3].w, fmaf(a[2], v[2].w, fmaf(a[1], v[1].w, a[0] * v[0].w)))) * inv;

    // stage transposed output tile in smem
    sm_o[4 * c4 + 0][px] = o.x;
    sm_o[4 * c4 + 1][px] = o.y;
    sm_o[4 * c4 + 2][px] = o.z;
    sm_o[4 * c4 + 3][px] = o.w;
    __syncthreads();

    // coalesced writeout: warp w covers channels 4w..4w+3
    float* ob = out + (size_t)b * Cc * HWc + p0;
    #pragma unroll
    for (int i2 = 0; i2 < 4; i2++) {
        int c = wrp * 4 + i2;
        ob[(size_t)c * HWc + lane] = sm_o[c][lane];
    }
}

// ---------------------------------------------------------------------------
// Launch
// ---------------------------------------------------------------------------
extern "C" void kernel_launch(void* const* d_in, const int* in_sizes, int n_in,
                              void* d_out, int out_size) {
    const float* x0    = (const float*)d_in[0];
    const float* x1    = (const float*)d_in[1];
    const float* pt    = (const float*)d_in[2];
    const float* mlp_w = (const float*)d_in[3];
    const float* mlp_b = (const float*)d_in[4];
    float* out = (float*)d_out;

    theta_kernel<<<1, 32>>>(pt);

    dim3 blkS(SPX, SCG);
    dim3 gridS(HWc / SPX, Bc);
    score_kernel<<<gridS, blkS>>>(x0, x1, mlp_w, mlp_b);

    dim3 gridB((HWc + 255) / 256, Bc);
    dilate_kernel<<<gridB, 256>>>();

    dim3 gridF(HWc / GPX, Bc);
    fuse_kernel<<<gridF, 512>>>(out);
}